// round 11
// baseline (speedup 1.0000x reference)
#include <cuda_runtime.h>
#include <cuda_fp16.h>
#include <cstdint>

#define BB 2
#define FF 48
#define CC 96
#define HH 320
#define WW 320
#define HWW (HH*WW)

#define STRIP 128
#define NSTRIP (HWW/STRIP)   // 800
#define NJOBS (NSTRIP*BB)    // 1600
#define CHUNK 16
#define NCH (CC/CHUNK)       // 6
#define NCTAS 148

// smem: B weights (unswizzled, k-permuted rows) | 3 A buffers (XOR-swizzled) | s_sig
#define SB_BYTES (NCH*9*CC*32)             // 165888
#define ABUF_BYTES 12800                   // 390 rows * 32B, padded to 256B
#define SA_OFF SB_BYTES
#define SSIG_OFF (SB_BYTES + 3*ABUF_BYTES) // 204288
#define SSIG_BYTES (STRIP*CC*2)            // 24576
#define SMEM_BYTES (SSIG_OFF + SSIG_BYTES) // 228864

// sigma'd activations, fp16, pixel-interleaved by 16-ch chunk: [b][ci][pix][k16]
__device__ __align__(16) __half g_sig0[(size_t)BB*NCH*HWW*CHUNK];
__device__ __align__(16) __half g_sig1[(size_t)BB*NCH*HWW*CHUNK];
// weights: fp16, [ci][tap][cout96][k16], k-permuted per row
__device__ float  g_w0[2*9*CC];
__device__ __align__(16) __half g_w1[NCH*9*CC*CHUNK];
__device__ __align__(16) __half g_w2[NCH*9*CC*CHUNK];
__device__ float g_b0[CC];
__device__ float g_b1[CC];
__device__ float g_b2[CC];

__device__ __forceinline__ float sigma_f(float u) {
    float quad = fmaf(u, fmaf(u, 250.0f, 0.5f), 0.00025f);
    return (fabsf(u) > 0.001f) ? fmaxf(u, 0.0f) : quad;
}

// k permutation within a 16-half B row: qid-block q holds {2q,2q+1,2q+8,2q+9}
__device__ __host__ __forceinline__ int kpos(int k) {
    return (k < 8) ? ((k >> 1)*4 + (k & 1)) : (((k - 8) >> 1)*4 + 2 + (k & 1));
}

// A-region 16B XOR swizzle (conflict-free ldmatrix over 32B-stride rows)
__device__ __forceinline__ uint32_t swz(uint32_t off) {
    return off ^ ((off & 128u) >> 3);
}

__device__ __forceinline__ uint32_t smem_u32(const void* p) {
    return (uint32_t)__cvta_generic_to_shared(p);
}
__device__ __forceinline__ void lds64(uint32_t& a, uint32_t& b, uint32_t addr) {
    asm volatile("ld.shared.v2.b32 {%0,%1}, [%2];" : "=r"(a), "=r"(b) : "r"(addr));
}
__device__ __forceinline__ void ldmA(uint32_t* r, uint32_t addr) {
    asm volatile("ldmatrix.sync.aligned.m8n8.x4.shared.b16 {%0,%1,%2,%3}, [%4];"
        : "=r"(r[0]), "=r"(r[1]), "=r"(r[2]), "=r"(r[3]) : "r"(addr));
}
__device__ __forceinline__ void mma_f16(float* d, const uint32_t* a, const uint32_t* b) {
    asm("mma.sync.aligned.m16n8k16.row.col.f32.f16.f16.f32 "
        "{%0,%1,%2,%3}, {%4,%5,%6,%7}, {%8,%9}, {%0,%1,%2,%3};"
        : "+f"(d[0]), "+f"(d[1]), "+f"(d[2]), "+f"(d[3])
        : "r"(a[0]), "r"(a[1]), "r"(a[2]), "r"(a[3]), "r"(b[0]), "r"(b[1]));
}
__device__ __forceinline__ void cp16(uint32_t dst, const void* src, bool valid) {
    int sz = valid ? 16 : 0;
    asm volatile("cp.async.cg.shared.global [%0], [%1], 16, %2;"
                 :: "r"(dst), "l"(src), "r"(sz) : "memory");
}
#define CP_COMMIT() asm volatile("cp.async.commit_group;" ::: "memory")
#define CP_WAIT1()  asm volatile("cp.async.wait_group 1;" ::: "memory")

// ---------------------------------------------------------------------------
// Weight repack: complex (wr, wi) -> fp16 [ci][tap][cout][k16], k-permuted
// ---------------------------------------------------------------------------
__global__ void repack_big(const float* __restrict__ wr, const float* __restrict__ wi,
                           const float* __restrict__ br, const float* __restrict__ bi,
                           int which) {
    __half* dw = (which == 1) ? g_w1 : g_w2;
    float*  db = (which == 1) ? g_b1 : g_b2;
    int idx = blockIdx.x * blockDim.x + threadIdx.x;
    if (idx < CC) db[idx] = (idx < FF) ? br[idx] : bi[idx - FF];
    if (idx >= NCH*9*CC*CHUNK) return;
    int k    = idx % CHUNK;
    int cout = (idx / CHUNK) % CC;
    int t    = (idx / (CHUNK*CC)) % 9;
    int ci   = idx / (CHUNK*CC*9);
    int cin = ci*CHUNK + k;
    int fo = cout % FF, fi = cin % FF;
    const float* src = ((cout < FF) == (cin < FF)) ? wr : wi;
    float v = src[(fo*FF + fi)*9 + t];
    if (cout < FF && cin >= FF) v = -v;
    dw[(idx - k) + kpos(k)] = __float2half_rn(v);
}

__global__ void repack_small(const float* __restrict__ wr, const float* __restrict__ wi,
                             const float* __restrict__ br, const float* __restrict__ bi) {
    int idx = blockIdx.x * blockDim.x + threadIdx.x;
    if (idx < CC) g_b0[idx] = (idx < FF) ? br[idx] : bi[idx - FF];
    if (idx >= 2*9*CC) return;
    int cout = idx % CC;
    int t    = (idx / CC) % 9;
    int cin  = idx / (9*CC);
    int fo = cout % FF;
    const float* src = ((cout < FF) == (cin == 0)) ? wr : wi;
    float v = src[fo*9 + t];
    if (cout < FF && cin == 1) v = -v;
    g_w0[idx] = v;
}

// ---------------------------------------------------------------------------
// Layer 0: conv 2 -> 96, exact fp32; writes out + g_sig0 (half, interleaved)
// ---------------------------------------------------------------------------
__global__ __launch_bounds__(256)
void conv0_kernel(const float* __restrict__ xr, const float* __restrict__ xi,
                  float* __restrict__ out) {
    __shared__ float sw[2*9*CC];
    __shared__ float sb[CC];
    for (int i = threadIdx.x; i < 2*9*CC; i += 256) sw[i] = g_w0[i];
    if (threadIdx.x < CC) sb[threadIdx.x] = g_b0[threadIdx.x];
    __syncthreads();

    int pix = blockIdx.x * 256 + threadIdx.x;
    if (pix >= BB*HWW) return;
    int b = pix / HWW;
    int p = pix - b*HWW;
    int y = p / WW, x = p - y*WW;

    const float* x0 = xr + b*HWW;
    const float* x1 = xi + b*HWW;
    float in[18];
    #pragma unroll
    for (int dy = 0; dy < 3; dy++) {
        #pragma unroll
        for (int dx = 0; dx < 3; dx++) {
            int yy = y + dy - 1, xx = x + dx - 1;
            bool ok = (yy >= 0) && (yy < HH) && (xx >= 0) && (xx < WW);
            in[dy*3 + dx]     = ok ? x0[yy*WW + xx] : 0.0f;
            in[9 + dy*3 + dx] = ok ? x1[yy*WW + xx] : 0.0f;
        }
    }

    for (int ci = 0; ci < NCH; ci++) {
        uint32_t u[8];
        #pragma unroll
        for (int j2 = 0; j2 < 8; j2++) {
            float a2[2];
            #pragma unroll
            for (int s = 0; s < 2; s++) {
                int cout = ci*CHUNK + 2*j2 + s;
                float acc = sb[cout];
                #pragma unroll
                for (int t = 0; t < 18; t++)
                    acc = fmaf(in[t], sw[t*CC + cout], acc);
                int f = cout % FF, c2 = cout / FF;
                out[((b*FF + f)*HWW + p)*2 + c2] = acc;
                a2[s] = sigma_f(acc);
            }
            __half2 hh = __floats2half2_rn(a2[0], a2[1]);
            u[j2] = *reinterpret_cast<uint32_t*>(&hh);
        }
        uint4* dst = reinterpret_cast<uint4*>(
            g_sig0 + ((size_t)(b*NCH + ci)*HWW + p)*CHUNK);
        dst[0] = make_uint4(u[0], u[1], u[2], u[3]);
        dst[1] = make_uint4(u[4], u[5], u[6], u[7]);
    }
}

// ---------------------------------------------------------------------------
// Layers 1,2: persistent-weight fp16 m16n8k16 implicit GEMM,
// continuous cross-job cp.async pipeline (3 buffers, lookahead 2).
// Grid = 148 CTAs x 256 thr; each CTA loops ~11 strip jobs.
// Row-wrap at x=0/319 wrong by construction -> fixup repairs.
// ---------------------------------------------------------------------------
template<int LAYER>
__global__ __launch_bounds__(256, 1)
void convT_kernel(float* __restrict__ out) {
    extern __shared__ __align__(256) char smem_raw[];
    uint32_t sb_base = smem_u32(smem_raw);
    uint32_t sa_base[3] = { sb_base + SA_OFF, sb_base + SA_OFF + ABUF_BYTES,
                            sb_base + SA_OFF + 2*ABUF_BYTES };
    __half* s_sig = reinterpret_cast<__half*>(smem_raw + SSIG_OFF);

    const __half* __restrict__ sig_in = (LAYER == 1) ? g_sig0 : g_sig1;
    const __half* __restrict__ wg     = (LAYER == 1) ? g_w1 : g_w2;
    const float*  __restrict__ bg     = (LAYER == 1) ? g_b1 : g_b2;

    int tid  = threadIdx.x;
    int warp = tid >> 5, lane = tid & 31;
    int m0 = (warp >> 1) * 32;
    int n0 = (warp & 1) * 24;
    int gid = lane >> 2, qid = lane & 3;
    int arow = lane & 15;
    uint32_t akoff = (uint32_t)(lane >> 4) * 16;

    // stage ALL weights once (flat memcpy; k-perm pre-baked)
    {
        const uint4* srcw = reinterpret_cast<const uint4*>(wg);
        uint4* dstw = reinterpret_cast<uint4*>(smem_raw);
        for (int i = tid; i < SB_BYTES/16; i += 256) dstw[i] = srcw[i];
    }

    // hoisted biases for this warp's n-tile
    float brl[3][2], bil[3][2];
    #pragma unroll
    for (int nt = 0; nt < 3; nt++) {
        int n = n0 + nt*8 + 2*qid;
        brl[nt][0] = __ldg(bg + n);      brl[nt][1] = __ldg(bg + n + 1);
        bil[nt][0] = __ldg(bg + n + 48); bil[nt][1] = __ldg(bg + n + 49);
    }

    int myjobs = 1 + (NJOBS - 1 - (int)blockIdx.x) / (int)gridDim.x;
    int total  = myjobs * NCH;

    // rolling prefetch of linear chunk index l -> buffer l%3
    auto issue = [&](int l) {
        if (l < total) {
            int t  = l / NCH, ci = l - t*NCH;
            int job = (int)blockIdx.x + t*(int)gridDim.x;
            int jb = job / NSTRIP;
            int base = (job - jb*NSTRIP) * STRIP;
            const __half* pc = sig_in + ((size_t)jb*NCH + ci)*HWW*CHUNK;
            uint32_t ab = sa_base[l % 3];
            for (int i = tid; i < 2*390; i += 256) {
                int blk = i >> 1, hi = i & 1;
                int dyr = blk / 130, px = blk - dyr*130;
                int fl  = base + (dyr - 1)*WW + px - 1;
                bool ok = (fl >= 0) && (fl < HWW);
                cp16(ab + swz((uint32_t)(blk*32 + hi*16)),
                     pc + ((size_t)(ok ? fl : 0))*CHUNK + hi*8, ok);
            }
        }
        CP_COMMIT();
    };
    __syncthreads();         // weights staged before first MMA (and before any reuse)
    issue(0); issue(1);

    int l = 0;
    for (int t = 0; t < myjobs; t++) {
        int job = (int)blockIdx.x + t*(int)gridDim.x;
        int b     = job / NSTRIP;
        int base  = (job - b*NSTRIP) * STRIP;

        float acc[2][6][4];
        #pragma unroll
        for (int h = 0; h < 2; h++)
            #pragma unroll
            for (int nt = 0; nt < 6; nt++)
                #pragma unroll
                for (int r = 0; r < 4; r++) acc[h][nt][r] = 0.0f;

        for (int ci = 0; ci < NCH; ci++, l++) {
            CP_WAIT1();
            __syncthreads();

            uint32_t sa = sa_base[l % 3];
            uint32_t cioff = (uint32_t)ci * (9*CC*32);
            #pragma unroll
            for (int tap = 0; tap < 9; tap++) {
                int dy = tap / 3, dx = tap - dy*3;
                uint32_t boff = cioff + (uint32_t)tap * (CC*32);
                uint32_t bf[6][2];
                #pragma unroll
                for (int nt = 0; nt < 6; nt++) {
                    int nrow = ((nt < 3) ? (n0 + nt*8) : (48 + n0 + (nt-3)*8)) + gid;
                    lds64(bf[nt][0], bf[nt][1],
                          sb_base + boff + (uint32_t)nrow*32 + (uint32_t)qid*8);
                }
                #pragma unroll
                for (int h = 0; h < 2; h++) {
                    int p = dy*130 + dx + m0 + h*16 + arow;
                    uint32_t a[4];
                    ldmA(a, sa + swz((uint32_t)p*32 + akoff));
                    #pragma unroll
                    for (int nt = 0; nt < 6; nt++)
                        mma_f16(acc[h][nt], a, bf[nt]);
                }
            }
            issue(l + 2);   // prefetch 2 ahead (crosses job boundary)
        }

        // --- epilogue: direct float2 stores from fragments ---
        float2* ob = reinterpret_cast<float2*>(out)
                   + (size_t)(LAYER*BB + b)*FF*HWW + base;
        #pragma unroll
        for (int h = 0; h < 2; h++) {
            int m = m0 + h*16 + gid;
            #pragma unroll
            for (int nt = 0; nt < 3; nt++) {
                int n = n0 + nt*8 + 2*qid;
                float re0 = acc[h][nt][0] + brl[nt][0], re1 = acc[h][nt][1] + brl[nt][1];
                float re2 = acc[h][nt][2] + brl[nt][0], re3 = acc[h][nt][3] + brl[nt][1];
                float im0 = acc[h][nt+3][0] + bil[nt][0], im1 = acc[h][nt+3][1] + bil[nt][1];
                float im2 = acc[h][nt+3][2] + bil[nt][0], im3 = acc[h][nt+3][3] + bil[nt][1];
                ob[(size_t)n*HWW + m]         = make_float2(re0, im0);
                ob[(size_t)(n+1)*HWW + m]     = make_float2(re1, im1);
                ob[(size_t)n*HWW + m + 8]     = make_float2(re2, im2);
                ob[(size_t)(n+1)*HWW + m + 8] = make_float2(re3, im3);
                if (LAYER == 1) {
                    __half2* sg;
                    sg = reinterpret_cast<__half2*>(s_sig + m*CC + n);
                    *sg = __floats2half2_rn(sigma_f(re0), sigma_f(re1));
                    sg = reinterpret_cast<__half2*>(s_sig + m*CC + n + 48);
                    *sg = __floats2half2_rn(sigma_f(im0), sigma_f(im1));
                    sg = reinterpret_cast<__half2*>(s_sig + (m+8)*CC + n);
                    *sg = __floats2half2_rn(sigma_f(re2), sigma_f(re3));
                    sg = reinterpret_cast<__half2*>(s_sig + (m+8)*CC + n + 48);
                    *sg = __floats2half2_rn(sigma_f(im2), sigma_f(im3));
                }
            }
        }
        if (LAYER == 1) {
            __syncthreads();   // s_sig complete across warps
            for (int i = tid; i < NCH*STRIP; i += 256) {
                int ci = i >> 7;
                int px = i & (STRIP-1);
                const uint4* srcv = reinterpret_cast<const uint4*>(
                    s_sig + px*CC + ci*CHUNK);
                uint4* dst = reinterpret_cast<uint4*>(
                    g_sig1 + ((size_t)(b*NCH + ci)*HWW + base + px)*CHUNK);
                dst[0] = srcv[0];
                dst[1] = srcv[1];
            }
            // next write to s_sig is after NCH chunk-syncs of the next job
        }
    }
}

// ---------------------------------------------------------------------------
// Border fixup: recompute columns x=0 and x=319 for layer L (x-wrap repair).
// ---------------------------------------------------------------------------
template<int LAYER>
__global__ __launch_bounds__(96)
void fixup_kernel(float* __restrict__ out) {
    const __half* __restrict__ sig_in = (LAYER == 1) ? g_sig0 : g_sig1;
    const __half* __restrict__ wg     = (LAYER == 1) ? g_w1 : g_w2;
    const float*  __restrict__ bg     = (LAYER == 1) ? g_b1 : g_b2;

    int blk  = blockIdx.x;
    int side = blk & 1;
    int y    = (blk >> 1) % HH;
    int b    = (blk >> 1) / HH;
    int x    = side ? (WW-1) : 0;
    int xs   = side ? (WW-2) : 0;
    int cout = threadIdx.x;

    __shared__ float s_act[3][2][CC];
    for (int i = cout; i < 3*2*CC; i += 96) {
        int c   = i % CC;
        int dxl = (i / CC) % 2;
        int dy  = i / (2*CC);
        int yy  = y + dy - 1;
        float v = 0.0f;
        if (yy >= 0 && yy < HH)
            v = __half2float(sig_in[((size_t)(b*NCH + c/CHUNK)*HWW
                                     + yy*WW + xs + dxl)*CHUNK + (c % CHUNK)]);
        s_act[dy][dxl][c] = v;
    }
    __syncthreads();

    float acc = bg[cout];
    #pragma unroll
    for (int dy = 0; dy < 3; dy++)
        #pragma unroll
        for (int dx = 0; dx < 3; dx++) {
            int xx = x + dx - 1;
            if (xx < 0 || xx >= WW) continue;
            int dxl = xx - xs;
            for (int c = 0; c < CC; c++) {
                int row = ((c/CHUNK)*9 + dy*3 + dx)*CC + cout;
                float w = __half2float(wg[row*CHUNK + kpos(c % CHUNK)]);
                acc = fmaf(w, s_act[dy][dxl][c], acc);
            }
        }

    int p = y*WW + x;
    if (LAYER == 1)
        g_sig1[((size_t)(b*NCH + cout/CHUNK)*HWW + p)*CHUNK + (cout % CHUNK)]
            = __float2half_rn(sigma_f(acc));
    int f = cout % FF, c2 = cout / FF;
    out[(((size_t)(LAYER*BB + b)*FF + f)*HWW + p)*2 + c2] = acc;
}

extern "C" void kernel_launch(void* const* d_in, const int* in_sizes, int n_in,
                              void* d_out, int out_size) {
    const float* x_real = (const float*)d_in[0];
    const float* x_imag = (const float*)d_in[1];
    const float* w0r = (const float*)d_in[2];
    const float* w0i = (const float*)d_in[3];
    const float* b0r = (const float*)d_in[4];
    const float* b0i = (const float*)d_in[5];
    const float* w1r = (const float*)d_in[6];
    const float* w1i = (const float*)d_in[7];
    const float* b1r = (const float*)d_in[8];
    const float* b1i = (const float*)d_in[9];
    const float* w2r = (const float*)d_in[10];
    const float* w2i = (const float*)d_in[11];
    const float* b2r = (const float*)d_in[12];
    const float* b2i = (const float*)d_in[13];
    float* out = (float*)d_out;

    static bool attr_set = false;
    if (!attr_set) {
        cudaFuncSetAttribute(convT_kernel<1>, cudaFuncAttributeMaxDynamicSharedMemorySize, SMEM_BYTES);
        cudaFuncSetAttribute(convT_kernel<2>, cudaFuncAttributeMaxDynamicSharedMemorySize, SMEM_BYTES);
        attr_set = true;
    }

    repack_small<<<(2*9*CC + 255)/256, 256>>>(w0r, w0i, b0r, b0i);
    repack_big<<<(NCH*9*CC*CHUNK + 255)/256, 256>>>(w1r, w1i, b1r, b1i, 1);
    repack_big<<<(NCH*9*CC*CHUNK + 255)/256, 256>>>(w2r, w2i, b2r, b2i, 2);

    conv0_kernel<<<(BB*HWW + 255)/256, 256>>>(x_real, x_imag, out);

    convT_kernel<1><<<NCTAS, 256, SMEM_BYTES>>>(out);
    fixup_kernel<1><<<BB*HH*2, 96>>>(out);
    convT_kernel<2><<<NCTAS, 256, SMEM_BYTES>>>(out);
    fixup_kernel<2><<<BB*HH*2, 96>>>(out);
}